// round 13
// baseline (speedup 1.0000x reference)
#include <cuda_runtime.h>
#include <cstdint>
#include <cstddef>

#define NORB   9
#define NATOMS 384
#define NEDGES 6144
#define NKP    4
#define ALLN   (NATOMS * NORB)              // 3456
#define NFEAT  58
#define KELEM  (ALLN * ALLN)                // 11,943,936 floats per k-region
#define NCPLX  ((size_t)NKP * KELEM)        // 47,775,744
#define NITEM  (NEDGES + NATOMS)            // 6528
#define TWO_PI 6.283185307179586f

// 64-byte chunks (16 floats)
#define CHUNKS (NCPLX / 16)                 // 2,985,984
#define CPR    (ALLN / 16)                  // 216 chunks per matrix row
#define CPK    (KELEM / 16)                 // 746,496 chunks per k-region

// k_main grid: scatter blocks first, then fill blocks.
#define SCATB_PER_K 1479                    // 1479*256 = 6528*58 exact
#define NSCATB (SCATB_PER_K * NKP)          // 5916
#define NFILLB (CHUNKS / 256)               // 11664 exact
#define NGRID  (NSCATB + NFILLB)            // 17580

// Static feature -> (row, col, factor) maps for upper-tri orbital pairs
// l = [0,1,2], dims = [1,3,5], offsets = [0,1,4]
__constant__ unsigned char cROWS[NFEAT] = {
    0,
    0,0,0,
    0,0,0,0,0,
    1,1,1,2,2,2,3,3,3,
    1,1,1,1,1,2,2,2,2,2,3,3,3,3,3,
    4,4,4,4,4,5,5,5,5,5,6,6,6,6,6,7,7,7,7,7,8,8,8,8,8
};
__constant__ unsigned char cCOLS[NFEAT] = {
    0,
    1,2,3,
    4,5,6,7,8,
    1,2,3,1,2,3,1,2,3,
    4,5,6,7,8,4,5,6,7,8,4,5,6,7,8,
    4,5,6,7,8,4,5,6,7,8,4,5,6,7,8,4,5,6,7,8,4,5,6,7,8
};
__constant__ float cFACS[NFEAT] = {
    0.5f,
    1.f,1.f,1.f,
    1.f,1.f,1.f,1.f,1.f,
    0.5f,0.5f,0.5f,0.5f,0.5f,0.5f,0.5f,0.5f,0.5f,
    1.f,1.f,1.f,1.f,1.f,1.f,1.f,1.f,1.f,1.f,1.f,1.f,1.f,1.f,1.f,
    0.5f,0.5f,0.5f,0.5f,0.5f,0.5f,0.5f,0.5f,0.5f,0.5f,0.5f,0.5f,0.5f,
    0.5f,0.5f,0.5f,0.5f,0.5f,0.5f,0.5f,0.5f,0.5f,0.5f,0.5f,0.5f
};

// Chunk bitmap: 1 byte per 64B output chunk. ~3 MB static scratch.
__device__ unsigned char g_bm[CHUNKS];

// Zero the bitmap (186,624 uint4 = 729*256 exact).
__global__ void k_bmz() {
    ((uint4*)g_bm)[blockIdx.x * 256 + threadIdx.x] = make_uint4(0u,0u,0u,0u);
}

// Mark every 64B chunk that receives any contribution. Thread = (item, k).
__global__ void k_mark(const int* __restrict__ eidx) {
    const int t = blockIdx.x * blockDim.x + threadIdx.x;
    if (t >= NITEM * NKP) return;
    const int w = t >> 2;
    const int k = t & 3;

    int a, b;
    if (w < NEDGES) { a = eidx[w]; b = eidx[NEDGES + w]; }
    else            { a = w - NEDGES; b = a; }
    if ((unsigned)a >= NATOMS || (unsigned)b >= NATOMS) return;

    const int kbase = k * CPK;
    #pragma unroll
    for (int r = 0; r < NORB; ++r) {
        // block (a,b): rows a*9+r, cols [b*9, b*9+9)
        {
            const int base = kbase + (a * NORB + r) * CPR;
            g_bm[base + ((b * NORB)     >> 4)] = 1;
            g_bm[base + ((b * NORB + 8) >> 4)] = 1;
        }
        // block (b,a): rows b*9+r, cols [a*9, a*9+9)
        {
            const int base = kbase + (b * NORB + r) * CPR;
            g_bm[base + ((a * NORB)     >> 4)] = 1;
            g_bm[base + ((a * NORB + 8) >> 4)] = 1;
        }
    }
}

// Zero exactly the marked chunks (unique writes; ~12 MB). Leaves them L2-hot
// for the REDs in k_main.
__global__ void k_zmark(float* __restrict__ out) {
    const int c = blockIdx.x * 256 + threadIdx.x;
    if (!g_bm[c]) return;
    uint4* __restrict__ p = (uint4*)out + (size_t)c * 4;
    const uint4 z = make_uint4(0u,0u,0u,0u);
    p[0] = z; p[1] = z; p[2] = z; p[3] = z;
}

// Main kernel: scatter blocks RED into marked (pre-zeroed) chunks; fill
// blocks zero the unmarked chunks. The two halves are address-disjoint, so
// they need no synchronization and overlap fully.
__global__ __launch_bounds__(256) void k_main(
    const float* __restrict__ hop,     // [E, 58]
    const float* __restrict__ ons,     // [N, 58]
    const float* __restrict__ kpts,    // [4, 3]
    const int*   __restrict__ eidx,    // [2, E]
    const int*   __restrict__ eshift,  // [E, 3]
    float*       __restrict__ out)     // [4, 3456, 3456] float32 (real part)
{
    const int bid = blockIdx.x;
    const int tid = threadIdx.x;

    if (bid < NSCATB) {
        // ---------- scatter (same structure as the 19.8us R5 kernel) ----------
        const int k = bid / SCATB_PER_K;
        const int t = (bid - k * SCATB_PER_K) * 256 + tid;   // exact 6528*58
        const int w = t / NFEAT;
        const int f = t - w * NFEAT;
        const bool is_edge = (w < NEDGES);

        int ai, aj;
        float ph;                        // Re[exp(-2*pi*i k.R)]
        if (is_edge) {
            ai = eidx[w];
            aj = eidx[NEDGES + w];
            const float d = kpts[k * 3 + 0] * (float)eshift[w * 3 + 0]
                          + kpts[k * 3 + 1] * (float)eshift[w * 3 + 1]
                          + kpts[k * 3 + 2] * (float)eshift[w * 3 + 2];
            ph = __cosf(TWO_PI * d);
        } else {
            ai = w - NEDGES;
            aj = ai;
            ph = 1.f;
        }
        if ((unsigned)ai >= NATOMS || (unsigned)aj >= NATOMS) return;

        const float* __restrict__ src =
            is_edge ? (hop + (size_t)w * NFEAT)
                    : (ons + (size_t)(w - NEDGES) * NFEAT);
        const float v = cFACS[f] * src[f] * ph;

        const int r = ai * NORB + (int)cROWS[f];
        const int c = aj * NORB + (int)cCOLS[f];
        float* __restrict__ base = out + (size_t)k * KELEM;
        atomicAdd(base + (size_t)r * ALLN + c, v);   // Re(B)   at (r,c)
        atomicAdd(base + (size_t)c * ALLN + r, v);   // Re(B^H) at (c,r)
    } else {
        // ---------- fill unmarked chunks ----------
        const int c = (bid - NSCATB) * 256 + tid;    // exact CHUNKS coverage
        if (g_bm[c]) return;                          // marked: owned by k_zmark+REDs
        uint4* __restrict__ p = (uint4*)out + (size_t)c * 4;
        const uint4 z = make_uint4(0u,0u,0u,0u);
        p[0] = z; p[1] = z; p[2] = z; p[3] = z;
    }
}

// ---- complex64 fallback (unused for the f32 output; kept for safety) ----
__global__ __launch_bounds__(256, 8) void hr2hk_scatter_cplx(
    const float* __restrict__ hop, const float* __restrict__ ons,
    const float* __restrict__ kpts, const int* __restrict__ eidx,
    const int* __restrict__ eshift, float* __restrict__ out)
{
    const int w = blockIdx.x;
    const int t = threadIdx.x;
    if (t >= NFEAT * NKP) return;
    const int f = t >> 2;
    const int k = t & 3;
    const bool is_edge = (w < NEDGES);

    int ai, aj;
    float pre, pim;
    if (is_edge) {
        ai = eidx[w];
        aj = eidx[NEDGES + w];
        const float d = kpts[k * 3 + 0] * (float)eshift[w * 3 + 0]
                      + kpts[k * 3 + 1] * (float)eshift[w * 3 + 1]
                      + kpts[k * 3 + 2] * (float)eshift[w * 3 + 2];
        float s, c;
        __sincosf(TWO_PI * d, &s, &c);
        pre = c; pim = -s;
    } else {
        ai = w - NEDGES; aj = ai; pre = 1.f; pim = 0.f;
    }
    if ((unsigned)ai >= NATOMS || (unsigned)aj >= NATOMS) return;

    const float* __restrict__ src =
        is_edge ? (hop + (size_t)w * NFEAT)
                : (ons + (size_t)(w - NEDGES) * NFEAT);
    const float val = cFACS[f] * src[f];
    const float re = val * pre, im = val * pim;
    const int r = ai * NORB + (int)cROWS[f];
    const int c = aj * NORB + (int)cCOLS[f];
    const size_t kbase = (size_t)k * KELEM;
    float* p0 = out + 2 * (kbase + (size_t)r * ALLN + c);
    float* p1 = out + 2 * (kbase + (size_t)c * ALLN + r);
    atomicAdd(p0 + 0, re);
    atomicAdd(p0 + 1, im);
    atomicAdd(p1 + 0, re);
    atomicAdd(p1 + 1, -im);
}

__global__ void hr2hk_zero(uint4* __restrict__ out, size_t n_u4) {
    for (size_t i = (size_t)blockIdx.x * blockDim.x + threadIdx.x;
         i < n_u4; i += (size_t)gridDim.x * blockDim.x)
        out[i] = make_uint4(0u, 0u, 0u, 0u);
}

extern "C" void kernel_launch(void* const* d_in, const int* in_sizes, int n_in,
                              void* d_out, int out_size) {
    // Identify inputs by (pairwise-distinct) element counts, not position.
    const float* hop    = nullptr;
    const float* ons    = nullptr;
    const float* kpts   = nullptr;
    const int*   eidx   = nullptr;
    const int*   eshift = nullptr;

    for (int i = 0; i < n_in; ++i) {
        switch (in_sizes[i]) {
            case NEDGES * NFEAT: hop    = (const float*)d_in[i]; break;  // 356352
            case NATOMS * NFEAT: ons    = (const float*)d_in[i]; break;  // 22272
            case NKP * 3:        kpts   = (const float*)d_in[i]; break;  // 12
            case 2 * NEDGES:     eidx   = (const int*)d_in[i];   break;  // 12288
            case NEDGES * 3:     eshift = (const int*)d_in[i];   break;  // 18432
            default: break;
        }
    }
    if (!hop || !ons || !kpts || !eidx || !eshift) return;

    if ((long long)out_size == (long long)NCPLX) {
        // f32 real-part output: bitmap prep, zero marked chunks, then one
        // grid where fill (unmarked) and scatter (marked) run concurrently
        // on disjoint addresses.
        k_bmz<<<729, 256>>>();
        k_mark<<<(NITEM * NKP + 255) / 256, 256>>>(eidx);
        k_zmark<<<NFILLB, 256>>>((float*)d_out);
        k_main<<<NGRID, 256>>>(hop, ons, kpts, eidx, eshift, (float*)d_out);
    } else if ((long long)out_size == 2LL * (long long)NCPLX) {
        hr2hk_zero<<<8192, 256>>>((uint4*)d_out, NCPLX * 8 / 16);
        hr2hk_scatter_cplx<<<NEDGES + NATOMS, 256>>>(
            hop, ons, kpts, eidx, eshift, (float*)d_out);
    }
}

// round 14
// speedup vs baseline: 1.7084x; 1.7084x over previous
#include <cuda_runtime.h>
#include <cstdint>
#include <cstddef>

#define NORB   9
#define NATOMS 384
#define NEDGES 6144
#define NKP    4
#define ALLN   (NATOMS * NORB)              // 3456
#define NFEAT  58
#define KELEM  (ALLN * ALLN)                // 11,943,936 floats per k-region
#define NCPLX  ((size_t)NKP * KELEM)        // 47,775,744
#define NITEM  (NEDGES + NATOMS)            // 6528
#define NRUN   18                           // 9 direct rows + 9 transposed rows
#define TWO_PI 6.283185307179586f

// scatter grid: 6528 items * 4 k * 18 runs = 470016 = 1836 * 256 exact
#define SCAT_BLOCKS 1836

// Feature factors (0.5 on l-diagonal orbital pairs, else 1.0)
__constant__ float cFACS[NFEAT] = {
    0.5f,
    1.f,1.f,1.f,
    1.f,1.f,1.f,1.f,1.f,
    0.5f,0.5f,0.5f,0.5f,0.5f,0.5f,0.5f,0.5f,0.5f,
    1.f,1.f,1.f,1.f,1.f,1.f,1.f,1.f,1.f,1.f,1.f,1.f,1.f,1.f,1.f,
    0.5f,0.5f,0.5f,0.5f,0.5f,0.5f,0.5f,0.5f,0.5f,0.5f,0.5f,0.5f,0.5f,
    0.5f,0.5f,0.5f,0.5f,0.5f,0.5f,0.5f,0.5f,0.5f,0.5f,0.5f,0.5f
};

// Row-run tables for the 9x9 block pattern.
// Direct rows r: cols [c0, c0+len) are the populated (contiguous) entries.
__constant__ unsigned char cC0D [9] = {0,1,1,1,4,4,4,4,4};
__constant__ unsigned char cLenD[9] = {9,8,8,8,5,5,5,5,5};
// Transposed-block rows r: cols [0, len) populated (mirror of the pattern).
__constant__ unsigned char cLenT[9] = {1,4,4,4,9,9,9,9,9};

// feature index for populated pattern position (r,c); caller guarantees
// validity via the run tables.
__device__ __forceinline__ int fmap(int r, int c) {
    if (r == 0) return c;                       // (s,s)(s,p)(s,d): f 0..8
    if (r <= 3) {                               // p rows
        if (c >= 4) return 18 + (r - 1) * 5 + (c - 4);   // (p,d)
        return 9 + (r - 1) * 3 + (c - 1);                // (p,p)
    }
    return 33 + (r - 4) * 5 + (c - 4);          // (d,d)
}

__device__ __forceinline__ void red2(float* addr, float a, float b) {
    asm volatile("red.global.add.v2.f32 [%0], {%1, %2};"
                 :: "l"(addr), "f"(a), "f"(b) : "memory");
}

// Run-based scatter: thread = (item, k, run). Each thread gathers its run's
// <=9 contiguous values into registers and emits packed v2 + scalar REDs.
// Runs 0..8 = direct block rows at (ai, aj); 9..17 = transposed block rows
// at (aj, ai) (the Hermitian mirror; real part uses the same cos phase).
__global__ __launch_bounds__(256) void hr2hk_scat_v2(
    const float* __restrict__ hop,     // [E, 58]
    const float* __restrict__ ons,     // [N, 58]
    const float* __restrict__ kpts,    // [4, 3]
    const int*   __restrict__ eidx,    // [2, E]
    const int*   __restrict__ eshift,  // [E, 3]
    float*       __restrict__ out)     // [4, 3456, 3456] float32 (real part)
{
    const int t   = blockIdx.x * 256 + threadIdx.x;   // exact 6528*4*18
    const int w   = t / (NKP * NRUN);
    const int rem = t - w * (NKP * NRUN);
    const int k   = rem / NRUN;
    const int run = rem - k * NRUN;

    const bool is_edge = (w < NEDGES);

    int ai, aj;
    float ph;                          // Re[exp(-2*pi*i k.R)] = cos(2*pi k.R)
    if (is_edge) {
        ai = eidx[w];
        aj = eidx[NEDGES + w];
        const float d = kpts[k * 3 + 0] * (float)eshift[w * 3 + 0]
                      + kpts[k * 3 + 1] * (float)eshift[w * 3 + 1]
                      + kpts[k * 3 + 2] * (float)eshift[w * 3 + 2];
        ph = __cosf(TWO_PI * d);
    } else {
        ai = w - NEDGES;
        aj = ai;
        ph = 1.f;
    }
    if ((unsigned)ai >= NATOMS || (unsigned)aj >= NATOMS) return;

    const float* __restrict__ src =
        is_edge ? (hop + (size_t)w * NFEAT)
                : (ons + (size_t)(w - NEDGES) * NFEAT);

    int row, colbase, len;
    float v[9];
    if (run < 9) {
        // direct block row `run` of pattern at (ai, aj)
        const int rr = run;
        const int c0 = cC0D[rr];
        len     = cLenD[rr];
        row     = ai * NORB + rr;
        colbase = aj * NORB + c0;
        #pragma unroll
        for (int u = 0; u < 9; ++u) {
            if (u < len) {
                const int f = fmap(rr, c0 + u);
                v[u] = cFACS[f] * src[f] * ph;
            } else v[u] = 0.f;
        }
    } else {
        // transposed block row `rr` at (aj, ai): entry (rr, u) = pattern(u, rr)
        const int rr = run - 9;
        len     = cLenT[rr];
        row     = aj * NORB + rr;
        colbase = ai * NORB;
        #pragma unroll
        for (int u = 0; u < 9; ++u) {
            if (u < len) {
                const int f = fmap(u, rr);
                v[u] = cFACS[f] * src[f] * ph;
            } else v[u] = 0.f;
        }
    }

    float* __restrict__ p =
        out + (size_t)k * KELEM + (size_t)row * ALLN + colbase;

    // row*ALLN is even (ALLN=3456), so 8B alignment <=> (colbase+u) even.
    if ((colbase & 1) == 0) {
        #pragma unroll
        for (int u = 0; u < 9; u += 2) {
            if (u + 1 < len)      red2(p + u, v[u], v[u + 1]);
            else if (u < len)     atomicAdd(p + u, v[u]);
        }
    } else {
        atomicAdd(p, v[0]);                       // len >= 1 always
        #pragma unroll
        for (int u = 1; u < 9; u += 2) {
            if (u + 1 < len)      red2(p + u, v[u], v[u + 1]);
            else if (u < len)     atomicAdd(p + u, v[u]);
        }
    }
}

// ---- complex64 fallback (unused for the f32 output; kept for safety) ----
__constant__ unsigned char cROWS[NFEAT] = {
    0, 0,0,0, 0,0,0,0,0,
    1,1,1,2,2,2,3,3,3,
    1,1,1,1,1,2,2,2,2,2,3,3,3,3,3,
    4,4,4,4,4,5,5,5,5,5,6,6,6,6,6,7,7,7,7,7,8,8,8,8,8
};
__constant__ unsigned char cCOLS[NFEAT] = {
    0, 1,2,3, 4,5,6,7,8,
    1,2,3,1,2,3,1,2,3,
    4,5,6,7,8,4,5,6,7,8,4,5,6,7,8,
    4,5,6,7,8,4,5,6,7,8,4,5,6,7,8,4,5,6,7,8,4,5,6,7,8
};

__global__ __launch_bounds__(256, 8) void hr2hk_scatter_cplx(
    const float* __restrict__ hop, const float* __restrict__ ons,
    const float* __restrict__ kpts, const int* __restrict__ eidx,
    const int* __restrict__ eshift, float* __restrict__ out)
{
    const int w = blockIdx.x;
    const int t = threadIdx.x;
    if (t >= NFEAT * NKP) return;
    const int f = t >> 2;
    const int k = t & 3;
    const bool is_edge = (w < NEDGES);

    int ai, aj;
    float pre, pim;
    if (is_edge) {
        ai = eidx[w];
        aj = eidx[NEDGES + w];
        const float d = kpts[k * 3 + 0] * (float)eshift[w * 3 + 0]
                      + kpts[k * 3 + 1] * (float)eshift[w * 3 + 1]
                      + kpts[k * 3 + 2] * (float)eshift[w * 3 + 2];
        float s, c;
        __sincosf(TWO_PI * d, &s, &c);
        pre = c; pim = -s;
    } else {
        ai = w - NEDGES; aj = ai; pre = 1.f; pim = 0.f;
    }
    if ((unsigned)ai >= NATOMS || (unsigned)aj >= NATOMS) return;

    const float* __restrict__ src =
        is_edge ? (hop + (size_t)w * NFEAT)
                : (ons + (size_t)(w - NEDGES) * NFEAT);
    const float val = cFACS[f] * src[f];
    const float re = val * pre, im = val * pim;
    const int r = ai * NORB + (int)cROWS[f];
    const int c = aj * NORB + (int)cCOLS[f];
    const size_t kbase = (size_t)k * KELEM;
    float* p0 = out + 2 * (kbase + (size_t)r * ALLN + c);
    float* p1 = out + 2 * (kbase + (size_t)c * ALLN + r);
    atomicAdd(p0 + 0, re);
    atomicAdd(p0 + 1, im);
    atomicAdd(p1 + 0, re);
    atomicAdd(p1 + 1, -im);
}

__global__ void hr2hk_zero(uint4* __restrict__ out, size_t n_u4) {
    for (size_t i = (size_t)blockIdx.x * blockDim.x + threadIdx.x;
         i < n_u4; i += (size_t)gridDim.x * blockDim.x)
        out[i] = make_uint4(0u, 0u, 0u, 0u);
}

extern "C" void kernel_launch(void* const* d_in, const int* in_sizes, int n_in,
                              void* d_out, int out_size) {
    // Identify inputs by (pairwise-distinct) element counts, not position.
    const float* hop    = nullptr;
    const float* ons    = nullptr;
    const float* kpts   = nullptr;
    const int*   eidx   = nullptr;
    const int*   eshift = nullptr;

    for (int i = 0; i < n_in; ++i) {
        switch (in_sizes[i]) {
            case NEDGES * NFEAT: hop    = (const float*)d_in[i]; break;  // 356352
            case NATOMS * NFEAT: ons    = (const float*)d_in[i]; break;  // 22272
            case NKP * 3:        kpts   = (const float*)d_in[i]; break;  // 12
            case 2 * NEDGES:     eidx   = (const int*)d_in[i];   break;  // 12288
            case NEDGES * 3:     eshift = (const int*)d_in[i];   break;  // 18432
            default: break;
        }
    }
    if (!hop || !ons || !kpts || !eidx || !eshift) return;

    if ((long long)out_size == (long long)NCPLX) {
        // f32 real-part output: driver memset fill + vectorized RED scatter.
        cudaMemsetAsync(d_out, 0, NCPLX * sizeof(float), 0);
        hr2hk_scat_v2<<<SCAT_BLOCKS, 256>>>(
            hop, ons, kpts, eidx, eshift, (float*)d_out);
    } else if ((long long)out_size == 2LL * (long long)NCPLX) {
        hr2hk_zero<<<8192, 256>>>((uint4*)d_out, NCPLX * 8 / 16);
        hr2hk_scatter_cplx<<<NEDGES + NATOMS, 256>>>(
            hop, ons, kpts, eidx, eshift, (float*)d_out);
    }
}